// round 8
// baseline (speedup 1.0000x reference)
#include <cuda_runtime.h>

// ComNet: R=64 runs, T=256 timesteps, N=1024 agents, MLP 4->10(tanh)->2.
// Wavefront over B=4 agent blocks: thread with timestep role t computes block
// b = s - 2t at step s. 512-thread CTA = TWO independent runs in separate
// warp-halves (warps 0-7 / 8-15), each synced by its own named barrier so the
// scheduler interleaves the two runs' warps on each SMSP (stall hiding).

#define R_ 64
#define T_ 256
#define N_ 1024
#define NB_ 256                       // blocks per row (N/4)
#define NSTEP_ (2 * (T_ - 1) + NB_)   // 766 wavefront steps

__device__ __forceinline__ float htanh(float x) {
    float r; asm("tanh.approx.f32 %0, %1;" : "=f"(r) : "f"(x)); return r;
}

__global__ __launch_bounds__(512, 1)
void comnet_kernel(const float* __restrict__ runs,
                   const float* __restrict__ comm0,
                   const float* __restrict__ w1,
                   const float* __restrict__ b1,
                   const float* __restrict__ w2,
                   const float* __restrict__ b2,
                   float* __restrict__ out)
{
    const int tid  = threadIdx.x;
    const int half = tid >> 8;            // 0 or 1: which run
    const int t    = tid & 255;           // timestep role within the run
    const int lane = t & 31;
    const int warp = (t >> 5);            // 0..7 within the half
    const int r    = blockIdx.x * 2 + half;

    // per-half warp-boundary exchange ring
    __shared__ float4 ring[2][3][8];

    // ---- weights in registers ----
    float W1[40], B1[10], W2[20];
#pragma unroll
    for (int k = 0; k < 40; ++k) W1[k] = w1[k];
#pragma unroll
    for (int k = 0; k < 10; ++k) B1[k] = b1[k];
#pragma unroll
    for (int k = 0; k < 20; ++k) W2[k] = w2[k];
    const float B2lo = b2[0];
    const float B2hi = b2[1];

    const float4* __restrict__ xrow4 =
        (const float4*)(runs + ((size_t)r * T_ + t) * (size_t)N_ * 2);
    float4* __restrict__ orow4 = (float4*)(out + ((size_t)r * T_ + t) * N_);
    const float* __restrict__ c0row = comm0 + (size_t)r * N_;

    float4 h1 = make_float4(0.f, 0.f, 0.f, 0.f);   // own block @ s-1
    float4 h2 = h1;                                // own block @ s-2

    // rotating ring phases: p2=(s-2)%3, p1=(s-1)%3, p0=s%3
    int p0 = 0, p1 = 2, p2 = 1;

    const unsigned barid = half + 1;

    for (int s = 0; s < NSTEP_; ++s) {
        const int b = s - 2 * t;
        const bool active = ((unsigned)b < (unsigned)NB_);

        // ---- right values c(t-1, 4b+1..4b+4) ----
        float r0 = __shfl_up_sync(0xffffffffu, h2.y, 1);
        float r1 = __shfl_up_sync(0xffffffffu, h2.z, 1);
        float r2 = __shfl_up_sync(0xffffffffu, h2.w, 1);
        float r3 = __shfl_up_sync(0xffffffffu, h1.x, 1);
        if (lane == 0 && warp > 0) {
            float4 g2 = ring[half][p2][warp - 1];   // producer block @ s-2
            float4 g1 = ring[half][p1][warp - 1];   // producer block @ s-1
            r0 = g2.y; r1 = g2.z; r2 = g2.w; r3 = g1.x;
        }
        if (t == 0 && active) {                     // initial comm row
            const int base = 4 * b;
            r0 = c0row[base + 1];
            r1 = c0row[base + 2];
            r2 = c0row[base + 3];
            r3 = (b < NB_ - 1) ? c0row[base + 4] : 0.0f;
        }
        if (b == NB_ - 1) r3 = 0.0f;    // zero right boundary for agent N-1

        float4 cur = h1;
        if (active) {
            const float4 cx0 = xrow4[2 * b];        // direct loads (L1-resident)
            const float4 cx1 = xrow4[2 * b + 1];

            float o0v[4], o1v[4];
            float lf = (b == 0) ? 0.0f : h1.w;      // c(t, 4b-1)
#pragma unroll
            for (int k = 0; k < 4; ++k) {
                const float xx = (k == 0) ? cx0.x : (k == 1) ? cx0.z
                                : (k == 2) ? cx1.x : cx1.z;
                const float xy = (k == 0) ? cx0.y : (k == 1) ? cx0.w
                                : (k == 2) ? cx1.y : cx1.w;
                const float rt = (k == 0) ? r0 : (k == 1) ? r1
                                : (k == 2) ? r2 : r3;

                float a0 = B2lo, a0b = 0.f, a1 = B2hi, a1b = 0.f;
#pragma unroll
                for (int j = 0; j < 10; ++j) {
                    float a = fmaf(W1[4 * j + 0], xx, B1[j]);
                    a       = fmaf(W1[4 * j + 1], xy, a);
                    a       = fmaf(W1[4 * j + 3], rt, a);
                    a       = fmaf(W1[4 * j + 2], lf, a);   // lf last: shortest chain
                    const float h = htanh(a);               // MUFU.TANH
                    if (j & 1) { a0b = fmaf(W2[j], h, a0b); a1b = fmaf(W2[10 + j], h, a1b); }
                    else       { a0  = fmaf(W2[j], h, a0);  a1  = fmaf(W2[10 + j], h, a1); }
                }
                o0v[k] = a0 + a0b;
                const float o1 = a1 + a1b;
                o1v[k] = o1;
                lf = o1;                            // left-chain within block
            }
            orow4[b] = make_float4(o0v[0], o0v[1], o0v[2], o0v[3]);
            cur = make_float4(o1v[0], o1v[1], o1v[2], o1v[3]);
        }

        // publish warp-boundary block; shift history
        if (lane == 31 && active) ring[half][p0][warp] = cur;
        h2 = h1;
        if (active) h1 = cur;

        // rotate ring phases
        const int pn = p2;
        p2 = p1; p1 = p0; p0 = pn;

        // per-half named barrier: the two runs drift independently
        asm volatile("bar.sync %0, 256;" :: "r"(barid) : "memory");
    }
}

extern "C" void kernel_launch(void* const* d_in, const int* in_sizes, int n_in,
                              void* d_out, int out_size)
{
    const float* runs  = (const float*)d_in[0];
    const float* comm0 = (const float*)d_in[1];
    const float* w1    = (const float*)d_in[2];
    const float* b1    = (const float*)d_in[3];
    const float* w2    = (const float*)d_in[4];
    const float* b2    = (const float*)d_in[5];
    float* out = (float*)d_out;

    comnet_kernel<<<R_ / 2, 512>>>(runs, comm0, w1, b1, w2, b2, out);
}